// round 3
// baseline (speedup 1.0000x reference)
#include <cuda_runtime.h>
#include <cstdint>
#include <cstddef>

#define HH 1024
#define DD 256
#define BSz 1024
#define TS 256
#define K0T 1280
#define K1T 2048

// ---------- persistent device scratch ----------
__device__ __align__(128) float g_W0[3][HH * K0T];
__device__ __align__(128) float g_W1[3][HH * K1T];
__device__ __align__(128) float g_Wfc[DD * HH];
__device__ __align__(128) float g_C0[BSz * 3 * HH];
__device__ __align__(128) float g_base1[3 * HH];
__device__ __align__(128) float g_h0[BSz * HH];
__device__ __align__(128) float g_h1[BSz * HH];
__device__ __align__(128) float g_A0[2][BSz * K0T];
__device__ __align__(128) float g_A1[2][BSz * K1T];

// ---------- helpers ----------
__device__ __forceinline__ float tf32r(float x) {
    uint32_t u;
    asm("cvt.rna.tf32.f32 %0, %1;" : "=r"(u) : "f"(x));
    return __uint_as_float(u);
}

__device__ __forceinline__ void mma8(float (&c)[4], const uint32_t (&a)[4], uint32_t b0, uint32_t b1) {
    asm volatile(
        "mma.sync.aligned.m16n8k8.row.col.f32.tf32.tf32.f32 "
        "{%0,%1,%2,%3},{%4,%5,%6,%7},{%8,%9},{%0,%1,%2,%3};\n"
        : "+f"(c[0]), "+f"(c[1]), "+f"(c[2]), "+f"(c[3])
        : "r"(a[0]), "r"(a[1]), "r"(a[2]), "r"(a[3]), "r"(b0), "r"(b1));
}

__device__ __forceinline__ void cp16(float* sdst, const float* gsrc) {
    uint32_t s = (uint32_t)__cvta_generic_to_shared(sdst);
    asm volatile("cp.async.cg.shared.global [%0], [%1], 16;" :: "r"(s), "l"(gsrc));
}
__device__ __forceinline__ void cp_commit() { asm volatile("cp.async.commit_group;"); }
__device__ __forceinline__ void cp_wait0()  { asm volatile("cp.async.wait_group 0;"); }

__device__ __forceinline__ float sigm(float x) { return 1.f / (1.f + expf(-x)); }

// ---------- fused GRU GEMM stage (3 gate matrices share A fragments) ----------
__device__ __forceinline__ void gru_stage(const float* s, float (&aR)[2][4][4], float (&aZ)[2][4][4],
                                          float (&aN)[2][4][4], int wm, int wn, int g, int t4) {
    const float* sA = s;
    const float* sB = s + 128 * 36;
#pragma unroll
    for (int kk = 0; kk < 32; kk += 8) {
        uint32_t a[2][4];
#pragma unroll
        for (int i = 0; i < 2; i++) {
            const float* p = sA + (wm * 32 + i * 16 + g) * 36 + kk + t4;
            a[i][0] = __float_as_uint(p[0]);
            a[i][1] = __float_as_uint(p[8 * 36]);
            a[i][2] = __float_as_uint(p[4]);
            a[i][3] = __float_as_uint(p[8 * 36 + 4]);
        }
#pragma unroll
        for (int j = 0; j < 4; j++) {
            int o = (wn * 32 + j * 8 + g) * 36 + kk + t4;
            uint32_t b0, b1;
            b0 = __float_as_uint(sB[o]); b1 = __float_as_uint(sB[o + 4]);
            mma8(aR[0][j], a[0], b0, b1); mma8(aR[1][j], a[1], b0, b1);
            b0 = __float_as_uint(sB[64 * 36 + o]); b1 = __float_as_uint(sB[64 * 36 + o + 4]);
            mma8(aZ[0][j], a[0], b0, b1); mma8(aZ[1][j], a[1], b0, b1);
            b0 = __float_as_uint(sB[128 * 36 + o]); b1 = __float_as_uint(sB[128 * 36 + o + 4]);
            mma8(aN[0][j], a[0], b0, b1); mma8(aN[1][j], a[1], b0, b1);
        }
    }
}

template <int KT>
__device__ __forceinline__ void load_chunk(const float* A, const float* Wr, const float* Wz, const float* Wn,
                                           int k0, float* s, int m0, int n0, int tid) {
#pragma unroll
    for (int l = 0; l < 4; l++) {
        int q = tid + l * 256;
        int row = q >> 3, c4 = (q & 7) * 4;
        cp16(s + row * 36 + c4, A + (size_t)(m0 + row) * KT + k0 + c4);
    }
    const float* Ws[3] = {Wr, Wz, Wn};
#pragma unroll
    for (int gm = 0; gm < 3; gm++) {
        float* sb = s + 128 * 36 + gm * 64 * 36;
#pragma unroll
        for (int l = 0; l < 2; l++) {
            int q = tid + l * 256;
            int row = q >> 3, c4 = (q & 7) * 4;
            cp16(sb + row * 36 + c4, Ws[gm] + (size_t)(n0 + row) * KT + k0 + c4);
        }
    }
}

// ---------- fused GRU layer kernel ----------
// KT=1280 -> layer0 (A=[x|h0], C0 per-row consts). KT=2048 -> layer1 (A=[h0n|h1], base1 vec consts).
template <int KT, int KX>
__global__ void __launch_bounds__(256, 1) gru_kernel(int t, const float* __restrict__ vghn) {
    extern __shared__ float smem[];
    constexpr int NCH = KT / 32;
    constexpr int STAGE = (128 + 192) * 36;
    const int tid = threadIdx.x;
    const int lane = tid & 31, warp = tid >> 5;
    const int wm = warp >> 1, wn = warp & 1;
    const int g = lane >> 2, t4 = lane & 3;
    const int m0 = blockIdx.y * 128, n0 = blockIdx.x * 64;

    const float *A, *W0, *W1g, *W2;
    if (KT == K0T) { A = g_A0[t & 1]; W0 = g_W0[0]; W1g = g_W0[1]; W2 = g_W0[2]; }
    else           { A = g_A1[t & 1]; W0 = g_W1[0]; W1g = g_W1[1]; W2 = g_W1[2]; }

    float aR[2][4][4] = {}, aZ[2][4][4] = {}, aNi[2][4][4] = {}, aNh[2][4][4] = {};

    load_chunk<KT>(A, W0, W1g, W2, 0, smem, m0, n0, tid);
    cp_commit();
#pragma unroll 1
    for (int c = 0; c < NCH; c++) {
        float* s = smem + (c & 1) * STAGE;
        cp_wait0();
        __syncthreads();
        if (c + 1 < NCH) {
            load_chunk<KT>(A, W0, W1g, W2, (c + 1) * 32, smem + ((c + 1) & 1) * STAGE, m0, n0, tid);
            cp_commit();
        }
        if (c * 32 < KX) gru_stage(s, aR, aZ, aNi, wm, wn, g, t4);
        else             gru_stage(s, aR, aZ, aNh, wm, wn, g, t4);
    }

    const int nt = (t + 1) & 1;
#pragma unroll
    for (int i = 0; i < 2; i++) {
        int rb = m0 + wm * 32 + i * 16 + g;
#pragma unroll
        for (int j = 0; j < 4; j++) {
            int cc = n0 + wn * 32 + j * 8 + 2 * t4;
            float2 v1r = {0.f, 0.f}, v1z = {0.f, 0.f}, v1n = {0.f, 0.f};
            if (KT == K1T) {
                v1r = *(const float2*)(g_base1 + cc);
                v1z = *(const float2*)(g_base1 + HH + cc);
                v1n = *(const float2*)(g_base1 + 2 * HH + cc);
            }
            float2 vg = *(const float2*)(vghn + cc);
#pragma unroll
            for (int hf = 0; hf < 2; hf++) {
                int r = rb + hf * 8;
                float2 cm_r = {0.f, 0.f}, cm_z = {0.f, 0.f}, cm_n = {0.f, 0.f};
                if (KT == K0T) {
                    const float* cp = g_C0 + (size_t)r * 3 * HH + cc;
                    cm_r = *(const float2*)cp;
                    cm_z = *(const float2*)(cp + HH);
                    cm_n = *(const float2*)(cp + 2 * HH);
                }
                const float* hs = (KT == K0T) ? g_h0 : g_h1;
                float2 hp = *(const float2*)(hs + (size_t)r * HH + cc);
                float h[2];
#pragma unroll
                for (int e = 0; e < 2; e++) {
                    float pr  = aR[i][j][hf * 2 + e]  + (e ? cm_r.y : cm_r.x) + (e ? v1r.y : v1r.x);
                    float pz  = aZ[i][j][hf * 2 + e]  + (e ? cm_z.y : cm_z.x) + (e ? v1z.y : v1z.x);
                    float gin = aNi[i][j][hf * 2 + e] + (e ? cm_n.y : cm_n.x) + (e ? v1n.y : v1n.x);
                    float ghn = aNh[i][j][hf * 2 + e] + (e ? vg.y : vg.x);
                    float rr = sigm(pr);
                    float zz = sigm(pz);
                    float nn = tanhf(gin + rr * ghn);
                    float hv = e ? hp.y : hp.x;
                    h[e] = (1.f - zz) * nn + zz * hv;
                }
                float2 hw = {h[0], h[1]};
                float2 tw = {tf32r(h[0]), tf32r(h[1])};
                if (KT == K0T) {
                    *(float2*)(g_h0 + (size_t)r * HH + cc) = hw;
                    *(float2*)(g_A1[t & 1] + (size_t)r * K1T + cc) = tw;
                    *(float2*)(g_A0[nt] + (size_t)r * K0T + DD + cc) = tw;
                } else {
                    *(float2*)(g_h1 + (size_t)r * HH + cc) = hw;
                    *(float2*)(g_A1[nt] + (size_t)r * K1T + HH + cc) = tw;
                }
            }
        }
    }
}

// ---------- FC + activation + feedback kernel ----------
__global__ void __launch_bounds__(256, 1) fc_kernel(int t, const float* __restrict__ bfc, float* __restrict__ out) {
    __shared__ float fsm[2 * 128 * 36];  // two pipeline stages; reused as output staging
    const int tid = threadIdx.x;
    const int lane = tid & 31, warp = tid >> 5;
    const int wm = warp >> 2, wn = warp & 3;
    const int g = lane >> 2, t4 = lane & 3;
    const int m0 = blockIdx.y * 64, n0 = blockIdx.x * 64;
    const int nt = (t + 1) & 1;
    const float* A = g_A1[nt];  // h1n tf32 lives at column offset HH
    const int STG = 128 * 36;

    float acc[2][2][4] = {};

    auto ld = [&](int k0, float* s) {
#pragma unroll
        for (int l = 0; l < 2; l++) {
            int q = tid + l * 256;
            int row = q >> 3, c4 = (q & 7) * 4;
            cp16(s + row * 36 + c4, A + (size_t)(m0 + row) * K1T + HH + k0 + c4);
            cp16(s + 64 * 36 + row * 36 + c4, g_Wfc + (size_t)(n0 + row) * HH + k0 + c4);
        }
    };

    ld(0, fsm);
    cp_commit();
#pragma unroll 1
    for (int c = 0; c < 32; c++) {
        float* s = fsm + (c & 1) * STG;
        cp_wait0();
        __syncthreads();
        if (c + 1 < 32) { ld((c + 1) * 32, fsm + ((c + 1) & 1) * STG); cp_commit(); }
        const float* sA = s;
        const float* sB = s + 64 * 36;
#pragma unroll
        for (int kk = 0; kk < 32; kk += 8) {
            uint32_t a[2][4];
#pragma unroll
            for (int i = 0; i < 2; i++) {
                const float* p = sA + (wm * 32 + i * 16 + g) * 36 + kk + t4;
                a[i][0] = __float_as_uint(p[0]);
                a[i][1] = __float_as_uint(p[8 * 36]);
                a[i][2] = __float_as_uint(p[4]);
                a[i][3] = __float_as_uint(p[8 * 36 + 4]);
            }
#pragma unroll
            for (int j = 0; j < 2; j++) {
                int o = (wn * 16 + j * 8 + g) * 36 + kk + t4;
                uint32_t b0 = __float_as_uint(sB[o]), b1 = __float_as_uint(sB[o + 4]);
                mma8(acc[0][j], a[0], b0, b1);
                mma8(acc[1][j], a[1], b0, b1);
            }
        }
        __syncthreads();
    }

    // stage pre-activations (+ bias) into smem
#pragma unroll
    for (int i = 0; i < 2; i++)
#pragma unroll
        for (int j = 0; j < 2; j++)
#pragma unroll
            for (int hf = 0; hf < 2; hf++) {
                int r = wm * 32 + i * 16 + g + hf * 8;
                int cc = wn * 16 + j * 8 + 2 * t4;
                fsm[r * 66 + cc]     = acc[i][j][hf * 2]     + bfc[n0 + cc];
                fsm[r * 66 + cc + 1] = acc[i][j][hf * 2 + 1] + bfc[n0 + cc + 1];
            }
    __syncthreads();

    if (n0 == 0) {
        if (tid < 64) {
            int b = m0 + tid;
            float* row = fsm + tid * 66;
            float* op = out + (size_t)b * (TS * DD) + (size_t)t * DD;
            float* xp = g_A0[nt] + (size_t)b * K0T;
            // softmax [0,32)
            float mx = row[0];
            for (int c = 1; c < 32; c++) mx = fmaxf(mx, row[c]);
            float sum = 0.f;
            for (int c = 0; c < 32; c++) { float e = expf(row[c] - mx); row[c] = e; sum += e; }
            float inv = 1.f / sum;
            for (int c = 0; c < 32; c++) { float v = row[c] * inv; op[c] = v; xp[c] = tf32r(v); }
            // softmax [32,47)
            mx = row[32];
            for (int c = 33; c < 47; c++) mx = fmaxf(mx, row[c]);
            sum = 0.f;
            for (int c = 32; c < 47; c++) { float e = expf(row[c] - mx); row[c] = e; sum += e; }
            inv = 1.f / sum;
            for (int c = 32; c < 47; c++) { float v = row[c] * inv; op[c] = v; xp[c] = tf32r(v); }
            // sigmoid [47,64)
            for (int c = 47; c < 64; c++) { float v = sigm(row[c]); op[c] = v; xp[c] = tf32r(v); }
        }
    } else {
        for (int idx = tid; idx < 4096; idx += 256) {
            int r = idx >> 6, cc = idx & 63;
            int b = m0 + r, c = n0 + cc;
            float v = sigm(fsm[r * 66 + cc]);
            out[(size_t)b * (TS * DD) + (size_t)t * DD + c] = v;
            g_A0[nt][(size_t)b * K0T + c] = tf32r(v);
        }
    }
}

// ---------- C0 = glob @ W_ih0[:, :H].T + b_ih0 (+ b_hh0 for r,z) : fp32, once per replay ----------
__global__ void __launch_bounds__(256) c0_kernel(const float* __restrict__ emb, const float* __restrict__ Wih0,
                                                 const float* __restrict__ bih0, const float* __restrict__ bhh0) {
    __shared__ float As[16][64], Bs[16][64];
    int tid = threadIdx.x;
    int tx = tid & 15, ty = tid >> 4;
    int m0 = blockIdx.y * 64, n0 = blockIdx.x * 64;
    float acc[4][4] = {};
    for (int k0 = 0; k0 < HH; k0 += 16) {
#pragma unroll
        for (int l = 0; l < 4; l++) {
            int e = tid + l * 256;
            int rr = e >> 4, kk = e & 15;
            As[kk][rr] = emb[(size_t)(m0 + rr) * 3072 + k0 + kk];
            Bs[kk][rr] = Wih0[(size_t)(n0 + rr) * K0T + k0 + kk];
        }
        __syncthreads();
#pragma unroll
        for (int kk = 0; kk < 16; kk++) {
            float av[4], bv[4];
#pragma unroll
            for (int i = 0; i < 4; i++) av[i] = As[kk][ty * 4 + i];
#pragma unroll
            for (int j = 0; j < 4; j++) bv[j] = Bs[kk][tx * 4 + j];
#pragma unroll
            for (int i = 0; i < 4; i++)
#pragma unroll
                for (int j = 0; j < 4; j++) acc[i][j] += av[i] * bv[j];
        }
        __syncthreads();
    }
#pragma unroll
    for (int i = 0; i < 4; i++)
#pragma unroll
        for (int j = 0; j < 4; j++) {
            int r = m0 + ty * 4 + i, c = n0 + tx * 4 + j;
            g_C0[(size_t)r * 3072 + c] = acc[i][j] + bih0[c] + (c < 2 * HH ? bhh0[c] : 0.f);
        }
}

// ---------- setup kernels ----------
__global__ void pack_w0(const float* __restrict__ Wih0, const float* __restrict__ Whh0) {
    for (int idx = blockIdx.x * blockDim.x + threadIdx.x; idx < 3 * HH * K0T; idx += gridDim.x * blockDim.x) {
        int gr = idx / K0T;
        int k = idx - gr * K0T;
        float v = (k < DD) ? Wih0[(size_t)gr * K0T + HH + k] : Whh0[(size_t)gr * HH + (k - DD)];
        int gate = gr >> 10, n = gr & 1023;
        g_W0[gate][(size_t)n * K0T + k] = tf32r(v);
    }
}

__global__ void pack_w1(const float* __restrict__ Wih1, const float* __restrict__ Whh1) {
    for (int idx = blockIdx.x * blockDim.x + threadIdx.x; idx < 3 * HH * K1T; idx += gridDim.x * blockDim.x) {
        int gr = idx / K1T;
        int k = idx - gr * K1T;
        float v = (k < HH) ? Wih1[(size_t)gr * HH + k] : Whh1[(size_t)gr * HH + (k - HH)];
        int gate = gr >> 10, n = gr & 1023;
        g_W1[gate][(size_t)n * K1T + k] = tf32r(v);
    }
}

__global__ void pack_misc(const float* __restrict__ bih1, const float* __restrict__ bhh1,
                          const float* __restrict__ Wfc) {
    for (int i = blockIdx.x * blockDim.x + threadIdx.x; i < DD * HH; i += gridDim.x * blockDim.x) {
        g_Wfc[i] = tf32r(Wfc[i]);
        if (i < 3 * HH) g_base1[i] = bih1[i] + (i < 2 * HH ? bhh1[i] : 0.f);
    }
}

__global__ void init_kernel(const float* __restrict__ emb, const float* __restrict__ dyn) {
    for (int i = blockIdx.x * blockDim.x + threadIdx.x; i < BSz * HH; i += gridDim.x * blockDim.x) {
        int b = i >> 10, n = i & 1023;
        float h0 = emb[(size_t)b * 3072 + HH + n];
        float h1 = emb[(size_t)b * 3072 + 2 * HH + n];
        g_h0[i] = h0;
        g_h1[i] = h1;
        g_A0[0][(size_t)b * K0T + DD + n] = tf32r(h0);
        g_A1[0][(size_t)b * K1T + HH + n] = tf32r(h1);
        if (n < DD) g_A0[0][(size_t)b * K0T + n] = tf32r(dyn[(size_t)b * TS * DD + n]);
    }
}

// ---------- host ----------
extern "C" void kernel_launch(void* const* d_in, const int* in_sizes, int n_in,
                              void* d_out, int out_size) {
    const float* emb  = (const float*)d_in[0];
    const float* dyn  = (const float*)d_in[1];
    const float* Wih0 = (const float*)d_in[3];
    const float* Whh0 = (const float*)d_in[4];
    const float* bih0 = (const float*)d_in[5];
    const float* bhh0 = (const float*)d_in[6];
    const float* Wih1 = (const float*)d_in[7];
    const float* Whh1 = (const float*)d_in[8];
    const float* bih1 = (const float*)d_in[9];
    const float* bhh1 = (const float*)d_in[10];
    const float* Wfc  = (const float*)d_in[11];
    const float* bfc  = (const float*)d_in[12];
    float* out = (float*)d_out;

    const int SM = (128 + 192) * 36 * 2 * 4;  // 92160 bytes dynamic smem
    cudaFuncSetAttribute((const void*)gru_kernel<K0T, DD>, cudaFuncAttributeMaxDynamicSharedMemorySize, SM);
    cudaFuncSetAttribute((const void*)gru_kernel<K1T, HH>, cudaFuncAttributeMaxDynamicSharedMemorySize, SM);

    pack_w0<<<2048, 256>>>(Wih0, Whh0);
    pack_w1<<<2048, 256>>>(Wih1, Whh1);
    pack_misc<<<1024, 256>>>(bih1, bhh1, Wfc);
    init_kernel<<<2048, 256>>>(emb, dyn);
    c0_kernel<<<dim3(48, 16), 256>>>(emb, Wih0, bih0, bhh0);

    for (int t = 0; t < TS; t++) {
        gru_kernel<K0T, DD><<<dim3(16, 8), 256, SM>>>(t, bhh0 + 2 * HH);
        gru_kernel<K1T, HH><<<dim3(16, 8), 256, SM>>>(t, bhh1 + 2 * HH);
        fc_kernel<<<dim3(4, 16), 256>>>(t, bfc, out);
    }
}

// round 5
// speedup vs baseline: 2.4172x; 2.4172x over previous
#include <cuda_runtime.h>
#include <cuda_fp16.h>
#include <cstdint>
#include <cstddef>

#define HH 1024
#define DD 256
#define BSz 1024
#define TS 256
#define K0T 1280
#define K1T 2048

typedef __half h16;

// ---------------- persistent device scratch ----------------
__device__ __align__(256) h16   g_W0[3ull * HH * K0T];
__device__ __align__(256) h16   g_W1[3ull * HH * K1T];
__device__ __align__(256) h16   g_Wfc[(size_t)DD * HH];
__device__ __align__(256) float g_C0[(size_t)BSz * 3 * HH];
__device__ __align__(256) float g_base1[3 * HH];
__device__ __align__(256) float g_h0[(size_t)BSz * HH];
__device__ __align__(256) float g_h1[(size_t)BSz * HH];
__device__ __align__(256) h16   g_A0[2][(size_t)BSz * K0T];
__device__ __align__(256) h16   g_A1[2][(size_t)BSz * K1T];

// ---------------- helpers ----------------
__device__ __forceinline__ uint32_t smem_u32(const void* p) {
    return (uint32_t)__cvta_generic_to_shared(p);
}
__device__ __forceinline__ void cpa16(uint32_t d, const void* s) {
    asm volatile("cp.async.cg.shared.global [%0],[%1],16;" :: "r"(d), "l"(s));
}
#define CP_COMMIT() asm volatile("cp.async.commit_group;")
#define CP_WAIT1()  asm volatile("cp.async.wait_group 1;")
#define CP_WAIT0()  asm volatile("cp.async.wait_group 0;")

__device__ __forceinline__ void ldm4(uint32_t (&r)[4], uint32_t a) {
    asm volatile("ldmatrix.sync.aligned.m8n8.x4.shared.b16 {%0,%1,%2,%3},[%4];"
                 : "=r"(r[0]), "=r"(r[1]), "=r"(r[2]), "=r"(r[3]) : "r"(a));
}
__device__ __forceinline__ void ldm2(uint32_t (&r)[2], uint32_t a) {
    asm volatile("ldmatrix.sync.aligned.m8n8.x2.shared.b16 {%0,%1},[%2];"
                 : "=r"(r[0]), "=r"(r[1]) : "r"(a));
}
__device__ __forceinline__ void mma16(float (&c)[4], const uint32_t (&a)[4], uint32_t b0, uint32_t b1) {
    asm volatile("mma.sync.aligned.m16n8k16.row.col.f32.f16.f16.f32 "
                 "{%0,%1,%2,%3},{%4,%5,%6,%7},{%8,%9},{%0,%1,%2,%3};"
                 : "+f"(c[0]), "+f"(c[1]), "+f"(c[2]), "+f"(c[3])
                 : "r"(a[0]), "r"(a[1]), "r"(a[2]), "r"(a[3]), "r"(b0), "r"(b1));
}
__device__ __forceinline__ float fsigm(float x) { return __fdividef(1.f, 1.f + __expf(-x)); }

// swizzled smem byte offset for element (row, 8-elem chunk sub) with 128B rows
__device__ __forceinline__ uint32_t swz(int row, int sub) {
    return (uint32_t)(row * 128 + ((sub ^ (row & 7)) * 16));
}

// ---------------- GRU GEMM stage: K=64 chunk, warp tile 32x32 per gate ----------------
__device__ __forceinline__ void hstage(uint32_t st, float (&aR)[2][4][4], float (&aZ)[2][4][4],
                                       float (&aN)[2][4][4], int wm, int wn, int lane) {
#pragma unroll
    for (int kk = 0; kk < 4; kk++) {
        uint32_t af[2][4];
#pragma unroll
        for (int i = 0; i < 2; i++) {
            int r = wm * 32 + i * 16 + (lane & 15);
            ldm4(af[i], st + swz(r, 2 * kk + (lane >> 4)));
        }
        int nrow = wn * 32 + ((lane & 16) >> 1) + (lane & 7);
        int bch = 2 * kk + ((lane >> 3) & 1);
#pragma unroll
        for (int g = 0; g < 3; g++) {
            uint32_t sb = st + 16384 + g * 8192;
            float (&ac)[2][4][4] = (g == 0) ? aR : ((g == 1) ? aZ : aN);
#pragma unroll
            for (int j = 0; j < 2; j++) {
                uint32_t bf[4];
                ldm4(bf, sb + swz(nrow + j * 16, bch));
                mma16(ac[0][2 * j],     af[0], bf[0], bf[1]);
                mma16(ac[0][2 * j + 1], af[0], bf[2], bf[3]);
                mma16(ac[1][2 * j],     af[1], bf[0], bf[1]);
                mma16(ac[1][2 * j + 1], af[1], bf[2], bf[3]);
            }
        }
    }
}

// ---------------- fused GRU layer kernel ----------------
// KT=1280 -> layer0 (A=[x|h0], per-row C0). KT=2048 -> layer1 (A=[h0n|h1], base1).
template <int KT, int KX>
__global__ void __launch_bounds__(256, 1) gru_hmma(int t, const float* __restrict__ vghn) {
    constexpr int NCH = KT / 64;
    constexpr int STAGE = 40960;
    extern __shared__ char dsm[];
    const int tid = threadIdx.x, lane = tid & 31, warp = tid >> 5;
    const int wm = warp >> 1, wn = warp & 1;
    const int m0 = blockIdx.y * 128, n0 = blockIdx.x * 64;
    const uint32_t sbase = smem_u32(dsm);

    const h16* A;
    const h16 *Wp[3];
    if (KT == K0T) {
        A = g_A0[t & 1];
        Wp[0] = g_W0; Wp[1] = g_W0 + (size_t)HH * K0T; Wp[2] = g_W0 + 2ull * HH * K0T;
    } else {
        A = g_A1[t & 1];
        Wp[0] = g_W1; Wp[1] = g_W1 + (size_t)HH * K1T; Wp[2] = g_W1 + 2ull * HH * K1T;
    }

    auto load_chunk = [&](int c) {
        uint32_t st = sbase + (c & 1) * STAGE;
        int kb = c * 64;
#pragma unroll
        for (int l = 0; l < 10; l++) {
            int q = tid + l * 256;
            if (q < 1024) {
                int row = q >> 3, sub = q & 7;
                cpa16(st + swz(row, sub), A + (size_t)(m0 + row) * KT + kb + sub * 8);
            } else {
                int q2 = q - 1024;
                int gate = q2 >> 9, r2 = q2 & 511;
                int row = r2 >> 3, sub = r2 & 7;
                cpa16(st + 16384 + gate * 8192 + swz(row, sub),
                      Wp[gate] + (size_t)(n0 + row) * KT + kb + sub * 8);
            }
        }
        CP_COMMIT();
    };

    float aR[2][4][4] = {}, aZ[2][4][4] = {}, aNi[2][4][4] = {}, aNh[2][4][4] = {};

    load_chunk(0);
#pragma unroll 1
    for (int c = 0; c < NCH; c++) {
        if (c + 1 < NCH) { load_chunk(c + 1); CP_WAIT1(); }
        else             { CP_WAIT0(); }
        __syncthreads();
        uint32_t st = sbase + (c & 1) * STAGE;
        if (c * 64 < KX) hstage(st, aR, aZ, aNi, wm, wn, lane);
        else             hstage(st, aR, aZ, aNh, wm, wn, lane);
        __syncthreads();
    }

    const int nt = (t + 1) & 1;
    const int g4 = lane >> 2, t4 = lane & 3;
    float* hs = (KT == K0T) ? g_h0 : g_h1;
#pragma unroll
    for (int i = 0; i < 2; i++) {
        int rb = m0 + wm * 32 + i * 16 + g4;
#pragma unroll
        for (int j = 0; j < 4; j++) {
            int cc = n0 + wn * 32 + j * 8 + 2 * t4;
            float2 v1r = {0.f, 0.f}, v1z = {0.f, 0.f}, v1n = {0.f, 0.f};
            if (KT == K1T) {
                v1r = *(const float2*)(g_base1 + cc);
                v1z = *(const float2*)(g_base1 + HH + cc);
                v1n = *(const float2*)(g_base1 + 2 * HH + cc);
            }
            float2 vg = *(const float2*)(vghn + cc);
#pragma unroll
            for (int hf = 0; hf < 2; hf++) {
                int r = rb + hf * 8;
                float2 cm_r = v1r, cm_z = v1z, cm_n = v1n;
                if (KT == K0T) {
                    const float* cp = g_C0 + (size_t)r * 3072 + cc;
                    cm_r = *(const float2*)cp;
                    cm_z = *(const float2*)(cp + HH);
                    cm_n = *(const float2*)(cp + 2 * HH);
                }
                float2 hp = *(const float2*)(hs + (size_t)r * HH + cc);
                float h[2];
#pragma unroll
                for (int e = 0; e < 2; e++) {
                    float pr  = aR[i][j][hf * 2 + e]  + (e ? cm_r.y : cm_r.x);
                    float pz  = aZ[i][j][hf * 2 + e]  + (e ? cm_z.y : cm_z.x);
                    float gin = aNi[i][j][hf * 2 + e] + (e ? cm_n.y : cm_n.x);
                    float ghn = aNh[i][j][hf * 2 + e] + (e ? vg.y : vg.x);
                    float rr = fsigm(pr);
                    float zz = fsigm(pz);
                    float nn = tanhf(gin + rr * ghn);
                    float hv = e ? hp.y : hp.x;
                    h[e] = (1.f - zz) * nn + zz * hv;
                }
                *(float2*)(hs + (size_t)r * HH + cc) = make_float2(h[0], h[1]);
                __half2 hh = __floats2half2_rn(h[0], h[1]);
                if (KT == K0T) {
                    *(__half2*)(g_A1[t & 1] + (size_t)r * K1T + cc) = hh;
                    *(__half2*)(g_A0[nt] + (size_t)r * K0T + DD + cc) = hh;
                } else {
                    *(__half2*)(g_A1[nt] + (size_t)r * K1T + HH + cc) = hh;
                }
            }
        }
    }
}

// ---------------- FC + activation + feedback (fp16, BM=64 BN=32 K=1024) ----------------
__global__ void __launch_bounds__(256, 1) fc_hmma(int t, const float* __restrict__ bfc, float* __restrict__ out) {
    constexpr int STAGE = 12288;  // A 8KB + B 4KB
    extern __shared__ char dsm[];
    const int tid = threadIdx.x, lane = tid & 31, warp = tid >> 5;
    const int wm = warp >> 2, wn = warp & 3;
    const int m0 = blockIdx.y * 64, n0 = blockIdx.x * 32;
    const int nt = (t + 1) & 1;
    const uint32_t sbase = smem_u32(dsm);
    const h16* A = g_A1[nt];  // h1n at col offset HH

    auto load_chunk = [&](int c) {
        uint32_t st = sbase + (c & 1) * STAGE;
        int kb = c * 64;
#pragma unroll
        for (int l = 0; l < 3; l++) {
            int q = tid + l * 256;
            if (q < 512) {
                int row = q >> 3, sub = q & 7;
                cpa16(st + swz(row, sub), A + (size_t)(m0 + row) * K1T + HH + kb + sub * 8);
            } else {
                int q2 = q - 512;
                int row = q2 >> 3, sub = q2 & 7;
                cpa16(st + 8192 + swz(row, sub), g_Wfc + (size_t)(n0 + row) * HH + kb + sub * 8);
            }
        }
        CP_COMMIT();
    };

    float acc[2][4] = {};

    load_chunk(0);
#pragma unroll 1
    for (int c = 0; c < 16; c++) {
        if (c + 1 < 16) { load_chunk(c + 1); CP_WAIT1(); }
        else            { CP_WAIT0(); }
        __syncthreads();
        uint32_t st = sbase + (c & 1) * STAGE;
#pragma unroll
        for (int kk = 0; kk < 4; kk++) {
            uint32_t af[2][4];
#pragma unroll
            for (int i = 0; i < 2; i++) {
                int r = wm * 32 + i * 16 + (lane & 15);
                ldm4(af[i], st + swz(r, 2 * kk + (lane >> 4)));
            }
            int nrow = wn * 8 + (lane & 7);
            int bch = 2 * kk + ((lane >> 3) & 1);
            uint32_t bf[2];
            ldm2(bf, st + 8192 + swz(nrow, bch));
            mma16(acc[0], af[0], bf[0], bf[1]);
            mma16(acc[1], af[1], bf[0], bf[1]);
        }
        __syncthreads();
    }

    // stage pre-activations (+bias) into smem: 64 rows x 34 floats
    float* fsm = (float*)dsm;
    const int g4 = lane >> 2, t4 = lane & 3;
#pragma unroll
    for (int i = 0; i < 2; i++)
#pragma unroll
        for (int hf = 0; hf < 2; hf++) {
            int r = wm * 32 + i * 16 + g4 + hf * 8;
            int cl = wn * 8 + 2 * t4;
            fsm[r * 34 + cl]     = acc[i][hf * 2]     + bfc[n0 + cl];
            fsm[r * 34 + cl + 1] = acc[i][hf * 2 + 1] + bfc[n0 + cl + 1];
        }
    __syncthreads();

    const int bx = blockIdx.x;
    if (bx == 0) {
        if (tid < 64) {
            int b = m0 + tid;
            float* row = fsm + tid * 34;
            float* op = out + (size_t)b * (TS * DD) + (size_t)t * DD;
            h16* xp = g_A0[nt] + (size_t)b * K0T;
            float mx = row[0];
            for (int c = 1; c < 32; c++) mx = fmaxf(mx, row[c]);
            float sum = 0.f;
            for (int c = 0; c < 32; c++) { float e = __expf(row[c] - mx); row[c] = e; sum += e; }
            float inv = __fdividef(1.f, sum);
            for (int c = 0; c < 32; c++) { float v = row[c] * inv; op[c] = v; xp[c] = __float2half_rn(v); }
        }
    } else if (bx == 1) {
        if (tid < 64) {
            int b = m0 + tid;
            float* row = fsm + tid * 34;
            float* op = out + (size_t)b * (TS * DD) + (size_t)t * DD + 32;
            h16* xp = g_A0[nt] + (size_t)b * K0T + 32;
            float mx = row[0];
            for (int c = 1; c < 15; c++) mx = fmaxf(mx, row[c]);
            float sum = 0.f;
            for (int c = 0; c < 15; c++) { float e = __expf(row[c] - mx); row[c] = e; sum += e; }
            float inv = __fdividef(1.f, sum);
            for (int c = 0; c < 15; c++) { float v = row[c] * inv; op[c] = v; xp[c] = __float2half_rn(v); }
            for (int c = 15; c < 32; c++) { float v = fsigm(row[c]); op[c] = v; xp[c] = __float2half_rn(v); }
        }
    } else {
        for (int idx = tid; idx < 2048; idx += 256) {
            int r = idx >> 5, cl = idx & 31;
            int b = m0 + r, c = n0 + cl;
            float v = fsigm(fsm[r * 34 + cl]);
            out[(size_t)b * (TS * DD) + (size_t)t * DD + c] = v;
            g_A0[nt][(size_t)b * K0T + c] = __float2half_rn(v);
        }
    }
}

// ---------------- C0 = glob @ W_ih0[:, :H].T + biases (fp32, once per replay) ----------------
__global__ void __launch_bounds__(256) c0_kernel(const float* __restrict__ emb, const float* __restrict__ Wih0,
                                                 const float* __restrict__ bih0, const float* __restrict__ bhh0) {
    __shared__ float As[16][64], Bs[16][64];
    int tid = threadIdx.x;
    int tx = tid & 15, ty = tid >> 4;
    int m0 = blockIdx.y * 64, n0 = blockIdx.x * 64;
    float acc[4][4] = {};
    for (int k0 = 0; k0 < HH; k0 += 16) {
#pragma unroll
        for (int l = 0; l < 4; l++) {
            int e = tid + l * 256;
            int rr = e >> 4, kk = e & 15;
            As[kk][rr] = emb[(size_t)(m0 + rr) * 3072 + k0 + kk];
            Bs[kk][rr] = Wih0[(size_t)(n0 + rr) * K0T + k0 + kk];
        }
        __syncthreads();
#pragma unroll
        for (int kk = 0; kk < 16; kk++) {
            float av[4], bv[4];
#pragma unroll
            for (int i = 0; i < 4; i++) av[i] = As[kk][ty * 4 + i];
#pragma unroll
            for (int j = 0; j < 4; j++) bv[j] = Bs[kk][tx * 4 + j];
#pragma unroll
            for (int i = 0; i < 4; i++)
#pragma unroll
                for (int j = 0; j < 4; j++) acc[i][j] += av[i] * bv[j];
        }
        __syncthreads();
    }
#pragma unroll
    for (int i = 0; i < 4; i++)
#pragma unroll
        for (int j = 0; j < 4; j++) {
            int r = m0 + ty * 4 + i, c = n0 + tx * 4 + j;
            g_C0[(size_t)r * 3072 + c] = acc[i][j] + bih0[c] + (c < 2 * HH ? bhh0[c] : 0.f);
        }
}

// ---------------- setup kernels ----------------
__global__ void pack_w0(const float* __restrict__ Wih0, const float* __restrict__ Whh0) {
    for (int idx = blockIdx.x * blockDim.x + threadIdx.x; idx < 3 * HH * K0T; idx += gridDim.x * blockDim.x) {
        int gr = idx / K0T;
        int k = idx - gr * K0T;
        float v = (k < DD) ? Wih0[(size_t)gr * K0T + HH + k] : Whh0[(size_t)gr * HH + (k - DD)];
        g_W0[idx] = __float2half_rn(v);
    }
}
__global__ void pack_w1(const float* __restrict__ Wih1, const float* __restrict__ Whh1) {
    for (int idx = blockIdx.x * blockDim.x + threadIdx.x; idx < 3 * HH * K1T; idx += gridDim.x * blockDim.x) {
        int gr = idx / K1T;
        int k = idx - gr * K1T;
        float v = (k < HH) ? Wih1[(size_t)gr * HH + k] : Whh1[(size_t)gr * HH + (k - HH)];
        g_W1[idx] = __float2half_rn(v);
    }
}
__global__ void pack_misc(const float* __restrict__ bih1, const float* __restrict__ bhh1,
                          const float* __restrict__ Wfc) {
    for (int i = blockIdx.x * blockDim.x + threadIdx.x; i < DD * HH; i += gridDim.x * blockDim.x) {
        g_Wfc[i] = __float2half_rn(Wfc[i]);
        if (i < 3 * HH) g_base1[i] = bih1[i] + (i < 2 * HH ? bhh1[i] : 0.f);
    }
}
__global__ void init_kernel(const float* __restrict__ emb, const float* __restrict__ dyn) {
    for (int i = blockIdx.x * blockDim.x + threadIdx.x; i < BSz * HH; i += gridDim.x * blockDim.x) {
        int b = i >> 10, n = i & 1023;
        float h0 = emb[(size_t)b * 3072 + HH + n];
        float h1 = emb[(size_t)b * 3072 + 2 * HH + n];
        g_h0[i] = h0;
        g_h1[i] = h1;
        g_A0[0][(size_t)b * K0T + DD + n] = __float2half_rn(h0);
        g_A1[0][(size_t)b * K1T + HH + n] = __float2half_rn(h1);
        if (n < DD) g_A0[0][(size_t)b * K0T + n] = __float2half_rn(dyn[(size_t)b * TS * DD + n]);
    }
}

// ---------------- host ----------------
extern "C" void kernel_launch(void* const* d_in, const int* in_sizes, int n_in,
                              void* d_out, int out_size) {
    const float* emb  = (const float*)d_in[0];
    const float* dyn  = (const float*)d_in[1];
    const float* Wih0 = (const float*)d_in[3];
    const float* Whh0 = (const float*)d_in[4];
    const float* bih0 = (const float*)d_in[5];
    const float* bhh0 = (const float*)d_in[6];
    const float* Wih1 = (const float*)d_in[7];
    const float* Whh1 = (const float*)d_in[8];
    const float* bih1 = (const float*)d_in[9];
    const float* bhh1 = (const float*)d_in[10];
    const float* Wfc  = (const float*)d_in[11];
    const float* bfc  = (const float*)d_in[12];
    float* out = (float*)d_out;

    const int SM = 2 * 40960;  // 81920 bytes dynamic smem
    cudaFuncSetAttribute((const void*)gru_hmma<K0T, DD>, cudaFuncAttributeMaxDynamicSharedMemorySize, SM);
    cudaFuncSetAttribute((const void*)gru_hmma<K1T, HH>, cudaFuncAttributeMaxDynamicSharedMemorySize, SM);
    const int SMF = 2 * 12288;
    cudaFuncSetAttribute((const void*)fc_hmma, cudaFuncAttributeMaxDynamicSharedMemorySize, SMF);

    pack_w0<<<2048, 256>>>(Wih0, Whh0);
    pack_w1<<<2048, 256>>>(Wih1, Whh1);
    pack_misc<<<1024, 256>>>(bih1, bhh1, Wfc);
    init_kernel<<<2048, 256>>>(emb, dyn);
    c0_kernel<<<dim3(48, 16), 256>>>(emb, Wih0, bih0, bhh0);

    for (int t = 0; t < TS; t++) {
        gru_hmma<K0T, DD><<<dim3(16, 8), 256, SM>>>(t, bhh0 + 2 * HH);
        gru_hmma<K1T, HH><<<dim3(16, 8), 256, SM>>>(t, bhh1 + 2 * HH);
        fc_hmma<<<dim3(8, 16), 256, SMF>>>(t, bfc, out);
    }
}